// round 10
// baseline (speedup 1.0000x reference)
#include <cuda_runtime.h>
#include <cuda_bf16.h>
#include <math.h>
#include <stdint.h>

#define BATCH     1024
#define NF        256
#define NS        100000
#define INV_TEMP  20.0f
#define LOG2E     1.4426950408889634f
#define LN2F      0.6931471805599453f
#define SCALE2    (INV_TEMP * LOG2E)           /* folded into A at prep */
#define SHIFT     128.0f                       /* fixed softmax shift (log2 domain) */
#define NTILE     256
#define NBLK      ((NS + NTILE - 1) / NTILE)   /* 391 */
#define MCHUNK    64
#define NCHUNKS   (BATCH / MCHUNK)             /* 16 */
#define LDSS      264                          /* 256 + 8 bf16 pad */

#define SM_A0     0                                    /* [64][264] bf16 = 33792 */
#define SM_A1     (MCHUNK * LDSS * 2)
#define SM_B      (2 * MCHUNK * LDSS * 2)              /* [256][264] bf16 = 135168 */
#define SMEM_BYTES (SM_B + NTILE * LDSS * 2 + 64)      /* ~203 KB */

__device__ __nv_bfloat16 g_a_bf16[BATCH * NF];   /* pre-scaled by SCALE2 */
__device__ float g_rowsum[BATCH];                /* REDG accumulation target */
__device__ float g_tlogit[BATCH];
__device__ int   g_tstride;

// ---------------------------------------------------------------- helpers
__device__ __forceinline__ uint32_t sptr(const void* p) {
    return (uint32_t)__cvta_generic_to_shared(p);
}
__device__ __forceinline__ void ldsm4(uint32_t addr, uint32_t& r0, uint32_t& r1,
                                      uint32_t& r2, uint32_t& r3) {
    asm volatile("ldmatrix.sync.aligned.m8n8.x4.shared.b16 {%0,%1,%2,%3}, [%4];"
                 : "=r"(r0), "=r"(r1), "=r"(r2), "=r"(r3) : "r"(addr));
}
__device__ __forceinline__ void mma16816(float c[4], const uint32_t a[4],
                                         uint32_t b0, uint32_t b1) {
    asm volatile(
        "mma.sync.aligned.m16n8k16.row.col.f32.bf16.bf16.f32 "
        "{%0,%1,%2,%3},{%4,%5,%6,%7},{%8,%9},{%0,%1,%2,%3};"
        : "+f"(c[0]), "+f"(c[1]), "+f"(c[2]), "+f"(c[3])
        : "r"(a[0]), "r"(a[1]), "r"(a[2]), "r"(a[3]), "r"(b0), "r"(b1));
}
#define CP_ASYNC16(dst, src) \
    asm volatile("cp.async.cg.shared.global [%0], [%1], 16;" :: "r"(dst), "l"(src) : "memory")
#define CP_COMMIT() asm volatile("cp.async.commit_group;" ::: "memory")
#define CP_WAIT1()  asm volatile("cp.async.wait_group 1;" ::: "memory")
#define CP_WAIT0()  asm volatile("cp.async.wait_group 0;" ::: "memory")

// ---------------------------------------------------------------- prep kernels
__global__ void prep_kernel(const float* __restrict__ a) {
    int i = blockIdx.x * blockDim.x + threadIdx.x;
    if (i < BATCH * NF) g_a_bf16[i] = __float2bfloat16(a[i] * SCALE2);
    if (blockIdx.x < 4) g_rowsum[blockIdx.x * 256 + threadIdx.x] = 0.f;
}

__global__ void detect_kernel(const int* __restrict__ t32) {
    if (threadIdx.x == 0 && blockIdx.x == 0) {
        int s = 2;
        for (int i = 1; i < 512; i += 2)
            if (t32[i] != 0) { s = 1; break; }
        g_tstride = s;
    }
}

__global__ void tlogit_kernel(const float* __restrict__ a,
                              const int* __restrict__ t32,
                              const float* __restrict__ f) {
    int row = blockIdx.x;
    int tid = threadIdx.x;  // 256
    long long tgt = (long long)t32[row * g_tstride];
    float p = a[row * NF + tid] * f[tgt * NF + tid];
    for (int off = 16; off; off >>= 1) p += __shfl_xor_sync(~0u, p, off);
    __shared__ float sm[8];
    if ((tid & 31) == 0) sm[tid >> 5] = p;
    __syncthreads();
    if (tid == 0) {
        float s = 0.f;
        #pragma unroll
        for (int w = 0; w < 8; w++) s += sm[w];
        g_tlogit[row] = s * INV_TEMP;
    }
}

// ---------------------------------------------------------------- chunk body
extern __shared__ char smem_raw[];

__device__ __forceinline__ void flush_quad(float sprev[4], int prow_base,
                                           int wm, int qr, int qc) {
    #pragma unroll
    for (int g = 0; g < 4; g++) {
        float s = sprev[g];
        s += __shfl_xor_sync(~0u, s, 1);
        s += __shfl_xor_sync(~0u, s, 2);
        if (qc == 0) {
            const int mf = g >> 1, hi = g & 1;
            const int rl = wm * 32 + mf * 16 + hi * 8 + qr;
            atomicAdd(&g_rowsum[prow_base + rl], s);
        }
    }
}

__device__ __forceinline__ void chunk_step(
    int mc,
    float (&accC)[2][8][4], float (&accP)[2][8][4],
    const uint32_t (&aAdB)[2], const uint32_t (&bAd)[4],
    char* adst,
    int tid, int wm, int wn, int qr, int qc)
{
    if (mc == NCHUNKS - 1) { CP_WAIT0(); } else { CP_WAIT1(); }
    __syncthreads();                      // A[mc] visible to all warps

    #pragma unroll
    for (int mf = 0; mf < 2; mf++)
        #pragma unroll
        for (int nf = 0; nf < 8; nf++)
            #pragma unroll
            for (int j = 0; j < 4; j++) accC[mf][nf][j] = 0.f;

    float sprev[4] = {0.f, 0.f, 0.f, 0.f};

    uint32_t af[2][2][4];
    uint32_t bf[2][8][2];
    #pragma unroll
    for (int t = 0; t < 2; t++)
        ldsm4(aAdB[t], af[0][t][0], af[0][t][1], af[0][t][2], af[0][t][3]);
    #pragma unroll
    for (int t = 0; t < 4; t++)
        ldsm4(bAd[t], bf[0][2*t][0], bf[0][2*t][1], bf[0][2*t+1][0], bf[0][2*t+1][1]);

    #pragma unroll
    for (int ks = 0; ks < 16; ks++) {
        const int cur = ks & 1, nx = cur ^ 1;
        if (ks < 15) {
            const uint32_t off = (uint32_t)(ks + 1) * 32;
            #pragma unroll
            for (int t = 0; t < 2; t++)
                ldsm4(aAdB[t] + off, af[nx][t][0], af[nx][t][1], af[nx][t][2], af[nx][t][3]);
            #pragma unroll
            for (int t = 0; t < 4; t++)
                ldsm4(bAd[t] + off, bf[nx][2*t][0], bf[nx][2*t][1], bf[nx][2*t+1][0], bf[nx][2*t+1][1]);
        }
        // interleaved epilogue: 4 exp2 of the previous chunk's accumulator per kstep
        #pragma unroll
        for (int t = 0; t < 4; t++) {
            const int e = ks * 4 + t;
            const int mf = e >> 5, r = e & 31;
            const int hi = r >> 4, nf = (r >> 1) & 7, j = r & 1;
            sprev[mf * 2 + hi] += exp2f(accP[mf][nf][hi * 2 + j] - SHIFT);
        }
        #pragma unroll
        for (int mf = 0; mf < 2; mf++)
            #pragma unroll
            for (int nf = 0; nf < 8; nf++)
                mma16816(accC[mf][nf], af[cur][mf], bf[cur][nf][0], bf[cur][nf][1]);
    }

    __syncthreads();                      // A[mc] buffer free for refill

    if (mc + 2 < NCHUNKS) {               // refill this buffer with A[mc+2]
        const char* src_base = (const char*)g_a_bf16 + (size_t)(mc + 2) * MCHUNK * 512;
        #pragma unroll
        for (int it = 0; it < 8; it++) {
            int i = tid + it * 256;
            int r = i >> 5, c8 = i & 31;
            CP_ASYNC16(sptr(adst + (r * LDSS + c8 * 8) * 2), src_base + (size_t)r * 512 + c8 * 16);
        }
        CP_COMMIT();
    }

    // finish prev chunk's softmax partials: quad-shfl + fire-and-forget REDG.
    // No barrier needed — nothing downstream reads these in this kernel.
    if (mc > 0)
        flush_quad(sprev, (mc - 1) * MCHUNK, wm, qr, qc);
}

// ---------------------------------------------------------------- fused GEMM + fixed-shift softmax partials
__global__ void __launch_bounds__(256, 1) gemm_lse_kernel(const float* __restrict__ feats) {
    __nv_bfloat16* Bs = (__nv_bfloat16*)(smem_raw + SM_B);

    const int tid  = threadIdx.x;                    // 256 threads, 8 warps
    const int lane = tid & 31, warp = tid >> 5;
    const int wm = warp & 1, wn = warp >> 1;         // 2x4 grid, 32x64 warp tiles
    const int nbase = blockIdx.x * NTILE;

    // Issue A chunks 0 and 1 (2-deep pipeline)
    #pragma unroll
    for (int pc = 0; pc < 2; pc++) {
        const char* src_base = (const char*)g_a_bf16 + (size_t)pc * MCHUNK * 512;
        char* dst = smem_raw + (pc ? SM_A1 : SM_A0);
        #pragma unroll
        for (int it = 0; it < 8; it++) {
            int i = tid + it * 256;
            int r = i >> 5, c8 = i & 31;
            CP_ASYNC16(sptr(dst + (r * LDSS + c8 * 8) * 2), src_base + (size_t)r * 512 + c8 * 16);
        }
        CP_COMMIT();
    }

    // Load feature slab once (fp32 -> bf16); OOB rows -> 0
    for (int i = tid; i < NTILE * (NF / 4); i += 256) {
        int r  = i >> 6;
        int c4 = i & 63;
        int srow = nbase + r;
        float4 v = make_float4(0.f, 0.f, 0.f, 0.f);
        if (srow < NS) v = ((const float4*)feats)[(size_t)srow * (NF / 4) + c4];
        __nv_bfloat162 p0 = __floats2bfloat162_rn(v.x, v.y);
        __nv_bfloat162 p1 = __floats2bfloat162_rn(v.z, v.w);
        uint2 u;
        u.x = *(uint32_t*)&p0;
        u.y = *(uint32_t*)&p1;
        *(uint2*)(Bs + r * LDSS + c4 * 4) = u;
    }

    const int aRow = lane & 15,                       aKo = (lane >> 4) << 3;
    const int bRow = (lane & 7) + ((lane >> 4) << 3), bKo = ((lane >> 3) & 1) << 3;
    const int qr = lane >> 2, qc = lane & 3;

    uint32_t aAd[2][2], bAd[4];
    #pragma unroll
    for (int t = 0; t < 2; t++) {
        aAd[0][t] = sptr(smem_raw + SM_A0 + ((wm * 32 + t * 16 + aRow) * LDSS + aKo) * 2);
        aAd[1][t] = aAd[0][t] + (SM_A1 - SM_A0);
    }
    #pragma unroll
    for (int t = 0; t < 4; t++)
        bAd[t] = sptr(Bs + (wn * 64 + t * 16 + bRow) * LDSS + bKo);

    float accA[2][8][4], accB[2][8][4];
    #pragma unroll
    for (int mf = 0; mf < 2; mf++)        // accB feeds chunk 0's (discarded) epilogue
        #pragma unroll
        for (int nf = 0; nf < 8; nf++)
            #pragma unroll
            for (int j = 0; j < 4; j++) accB[mf][nf][j] = 0.f;

    #pragma unroll 1
    for (int mc = 0; mc < NCHUNKS; mc += 2) {
        chunk_step(mc,     accA, accB, aAd[0], bAd, smem_raw + SM_A0, tid, wm, wn, qr, qc);
        chunk_step(mc + 1, accB, accA, aAd[1], bAd, smem_raw + SM_A1, tid, wm, wn, qr, qc);
    }

    // tail: epilogue of chunk NCHUNKS-1 (in accB); no barrier needed
    {
        float s4[4] = {0.f, 0.f, 0.f, 0.f};
        #pragma unroll
        for (int mf = 0; mf < 2; mf++)
            #pragma unroll
            for (int hi = 0; hi < 2; hi++)
                #pragma unroll
                for (int nf = 0; nf < 8; nf++)
                    #pragma unroll
                    for (int j = 0; j < 2; j++)
                        s4[mf * 2 + hi] += exp2f(accB[mf][nf][hi * 2 + j] - SHIFT);
        flush_quad(s4, (NCHUNKS - 1) * MCHUNK, wm, qr, qc);
    }
}

// ---------------------------------------------------------------- final: NLL + mean in one block
__global__ void final_kernel(float* __restrict__ out) {
    __shared__ float sm[32];
    int tid = threadIdx.x;  // 1024
    float v = (SHIFT + log2f(g_rowsum[tid])) * LN2F - g_tlogit[tid];
    for (int off = 16; off; off >>= 1) v += __shfl_xor_sync(~0u, v, off);
    if ((tid & 31) == 0) sm[tid >> 5] = v;
    __syncthreads();
    if (tid < 32) {
        float x = sm[tid];
        for (int off = 16; off; off >>= 1) x += __shfl_xor_sync(~0u, x, off);
        if (tid == 0) out[0] = x / (float)BATCH;
    }
}

// ---------------------------------------------------------------- launch
extern "C" void kernel_launch(void* const* d_in, const int* in_sizes, int n_in,
                              void* d_out, int out_size) {
    const float* a   = (const float*)d_in[0];   // inputs   [1024,256] f32
    const int*   t32 = (const int*)d_in[1];     // targets  [1024] i64/i32
    const float* f   = (const float*)d_in[2];   // features [100000,256] f32
    float* out = (float*)d_out;

    cudaFuncSetAttribute(gemm_lse_kernel,
                         cudaFuncAttributeMaxDynamicSharedMemorySize, SMEM_BYTES);

    prep_kernel<<<(BATCH * NF + 255) / 256, 256>>>(a);
    detect_kernel<<<1, 32>>>(t32);
    tlogit_kernel<<<BATCH, 256>>>(a, t32, f);
    gemm_lse_kernel<<<NBLK, 256, SMEM_BYTES>>>(f);
    final_kernel<<<1, 1024>>>(out);
}

// round 11
// speedup vs baseline: 1.0205x; 1.0205x over previous
#include <cuda_runtime.h>
#include <cuda_bf16.h>
#include <math.h>
#include <stdint.h>

#define BATCH     1024
#define NF        256
#define NS        100000
#define INV_TEMP  20.0f
#define LOG2E     1.4426950408889634f
#define LN2F      0.6931471805599453f
#define SCALE2    (INV_TEMP * LOG2E)           /* folded into A at prep */
#define SHIFT     128.0f                       /* fixed softmax shift (log2 domain) */
#define NTILE     256
#define NBLK      ((NS + NTILE - 1) / NTILE)   /* 391 */
#define MCHUNK    64
#define NCHUNKS   (BATCH / MCHUNK)             /* 16 */
#define LDSS      264                          /* 256 + 8 bf16 pad */
#define REDP      17                           /* padded red row: conflict-free */

#define SM_A0     0                                    /* [64][264] bf16 = 33792 */
#define SM_A1     (MCHUNK * LDSS * 2)
#define SM_B      (2 * MCHUNK * LDSS * 2)              /* [256][264] bf16 = 135168 */
#define SM_RED    (SM_B + NTILE * LDSS * 2)            /* [64][17] float */
#define SMEM_BYTES (SM_RED + MCHUNK * REDP * 4 + 64)   /* ~207 KB */

__device__ __nv_bfloat16 g_a_bf16[BATCH * NF];   /* pre-scaled by SCALE2 */
__device__ float g_ps[(size_t)NBLK * BATCH];
__device__ float g_tlogit[BATCH];
__device__ float g_rownll[BATCH];
__device__ int   g_tstride;

// ---------------------------------------------------------------- helpers
__device__ __forceinline__ uint32_t sptr(const void* p) {
    return (uint32_t)__cvta_generic_to_shared(p);
}
__device__ __forceinline__ void ldsm4(uint32_t addr, uint32_t& r0, uint32_t& r1,
                                      uint32_t& r2, uint32_t& r3) {
    asm volatile("ldmatrix.sync.aligned.m8n8.x4.shared.b16 {%0,%1,%2,%3}, [%4];"
                 : "=r"(r0), "=r"(r1), "=r"(r2), "=r"(r3) : "r"(addr));
}
__device__ __forceinline__ void mma16816(float c[4], const uint32_t a[4],
                                         uint32_t b0, uint32_t b1) {
    asm volatile(
        "mma.sync.aligned.m16n8k16.row.col.f32.bf16.bf16.f32 "
        "{%0,%1,%2,%3},{%4,%5,%6,%7},{%8,%9},{%0,%1,%2,%3};"
        : "+f"(c[0]), "+f"(c[1]), "+f"(c[2]), "+f"(c[3])
        : "r"(a[0]), "r"(a[1]), "r"(a[2]), "r"(a[3]), "r"(b0), "r"(b1));
}
#define CP_ASYNC16(dst, src) \
    asm volatile("cp.async.cg.shared.global [%0], [%1], 16;" :: "r"(dst), "l"(src) : "memory")
#define CP_COMMIT() asm volatile("cp.async.commit_group;" ::: "memory")
#define CP_WAIT1()  asm volatile("cp.async.wait_group 1;" ::: "memory")
#define CP_WAIT0()  asm volatile("cp.async.wait_group 0;" ::: "memory")

// ---------------------------------------------------------------- prep kernels
__global__ void prep_kernel(const float* __restrict__ a) {
    int i = blockIdx.x * blockDim.x + threadIdx.x;
    if (i < BATCH * NF) g_a_bf16[i] = __float2bfloat16(a[i] * SCALE2);
}

__global__ void detect_kernel(const int* __restrict__ t32) {
    if (threadIdx.x == 0 && blockIdx.x == 0) {
        int s = 2;
        for (int i = 1; i < 512; i += 2)
            if (t32[i] != 0) { s = 1; break; }
        g_tstride = s;
    }
}

__global__ void tlogit_kernel(const float* __restrict__ a,
                              const int* __restrict__ t32,
                              const float* __restrict__ f) {
    int row = blockIdx.x;
    int tid = threadIdx.x;  // 256
    long long tgt = (long long)t32[row * g_tstride];
    float p = a[row * NF + tid] * f[tgt * NF + tid];
    for (int off = 16; off; off >>= 1) p += __shfl_xor_sync(~0u, p, off);
    __shared__ float sm[8];
    if ((tid & 31) == 0) sm[tid >> 5] = p;
    __syncthreads();
    if (tid == 0) {
        float s = 0.f;
        #pragma unroll
        for (int w = 0; w < 8; w++) s += sm[w];
        g_tlogit[row] = s * INV_TEMP;
    }
}

// ---------------------------------------------------------------- chunk body
extern __shared__ char smem_raw[];

__device__ __forceinline__ void chunk_step(
    int mc,
    float (&accC)[2][8][4], float (&accP)[2][8][4],
    const uint32_t (&aAdB)[2], const uint32_t (&bAd)[4],
    char* adst, float* red_s,
    int tid, int wm, int wn, int qr, int qc)
{
    if (mc == NCHUNKS - 1) { CP_WAIT0(); } else { CP_WAIT1(); }
    __syncthreads();                      // A[mc] ready; prior red_s merge done

    #pragma unroll
    for (int mf = 0; mf < 2; mf++)
        #pragma unroll
        for (int nf = 0; nf < 8; nf++)
            #pragma unroll
            for (int j = 0; j < 4; j++) accC[mf][nf][j] = 0.f;

    float sprev[4] = {0.f, 0.f, 0.f, 0.f};

    uint32_t af[2][2][4];
    uint32_t bf[2][8][2];
    #pragma unroll
    for (int t = 0; t < 2; t++)
        ldsm4(aAdB[t], af[0][t][0], af[0][t][1], af[0][t][2], af[0][t][3]);
    #pragma unroll
    for (int t = 0; t < 4; t++)
        ldsm4(bAd[t], bf[0][2*t][0], bf[0][2*t][1], bf[0][2*t+1][0], bf[0][2*t+1][1]);

    #pragma unroll
    for (int ks = 0; ks < 16; ks++) {
        const int cur = ks & 1, nx = cur ^ 1;
        if (ks < 15) {
            const uint32_t off = (uint32_t)(ks + 1) * 32;
            #pragma unroll
            for (int t = 0; t < 2; t++)
                ldsm4(aAdB[t] + off, af[nx][t][0], af[nx][t][1], af[nx][t][2], af[nx][t][3]);
            #pragma unroll
            for (int t = 0; t < 4; t++)
                ldsm4(bAd[t] + off, bf[nx][2*t][0], bf[nx][2*t][1], bf[nx][2*t+1][0], bf[nx][2*t+1][1]);
        }
        // interleaved epilogue: 4 INDEPENDENT exp2 chains (one per sprev slot)
        {
            const int nf = ks >> 1, j = ks & 1;
            #pragma unroll
            for (int t = 0; t < 4; t++) {
                const int mf = t >> 1, hi = t & 1;
                sprev[t] += exp2f(accP[mf][nf][hi * 2 + j] - SHIFT);
            }
        }
        #pragma unroll
        for (int mf = 0; mf < 2; mf++)
            #pragma unroll
            for (int nf = 0; nf < 8; nf++)
                mma16816(accC[mf][nf], af[cur][mf], bf[cur][nf][0], bf[cur][nf][1]);
    }

    if (mc > 0) {                         // write prev chunk's per-quad sums
        #pragma unroll
        for (int t = 0; t < 4; t++) {
            const int mf = t >> 1, hi = t & 1;
            int rl = wm * 32 + mf * 16 + hi * 8 + qr;
            red_s[rl * REDP + wn * 4 + qc] = sprev[t];
        }
    }

    __syncthreads();                      // A[mc] free + red partials visible

    if (mc + 2 < NCHUNKS) {               // refill this buffer with A[mc+2]
        const char* src_base = (const char*)g_a_bf16 + (size_t)(mc + 2) * MCHUNK * 512;
        #pragma unroll
        for (int it = 0; it < 8; it++) {
            int i = tid + it * 256;
            int r = i >> 5, c8 = i & 31;
            CP_ASYNC16(sptr(adst + (r * LDSS + c8 * 8) * 2), src_base + (size_t)r * 512 + c8 * 16);
        }
        CP_COMMIT();
    }

    if (mc > 0 && tid < MCHUNK) {         // 16-way merge for prev chunk
        float S = red_s[tid * REDP];
        #pragma unroll
        for (int i = 1; i < 16; i++) S += red_s[tid * REDP + i];
        g_ps[(size_t)blockIdx.x * BATCH + (mc - 1) * MCHUNK + tid] = S;
    }
}

// ---------------------------------------------------------------- fused GEMM + fixed-shift softmax partials
__global__ void __launch_bounds__(256, 1) gemm_lse_kernel(const float* __restrict__ feats) {
    __nv_bfloat16* Bs = (__nv_bfloat16*)(smem_raw + SM_B);
    float* red_s = (float*)(smem_raw + SM_RED);

    const int tid  = threadIdx.x;                    // 256 threads, 8 warps
    const int lane = tid & 31, warp = tid >> 5;
    const int wm = warp & 1, wn = warp >> 1;         // 2x4 grid, 32x64 warp tiles
    const int nbase = blockIdx.x * NTILE;

    // Issue A chunks 0 and 1 (2-deep pipeline)
    #pragma unroll
    for (int pc = 0; pc < 2; pc++) {
        const char* src_base = (const char*)g_a_bf16 + (size_t)pc * MCHUNK * 512;
        char* dst = smem_raw + (pc ? SM_A1 : SM_A0);
        #pragma unroll
        for (int it = 0; it < 8; it++) {
            int i = tid + it * 256;
            int r = i >> 5, c8 = i & 31;
            CP_ASYNC16(sptr(dst + (r * LDSS + c8 * 8) * 2), src_base + (size_t)r * 512 + c8 * 16);
        }
        CP_COMMIT();
    }

    // Load feature slab once (fp32 -> bf16); OOB rows -> 0
    for (int i = tid; i < NTILE * (NF / 4); i += 256) {
        int r  = i >> 6;
        int c4 = i & 63;
        int srow = nbase + r;
        float4 v = make_float4(0.f, 0.f, 0.f, 0.f);
        if (srow < NS) v = ((const float4*)feats)[(size_t)srow * (NF / 4) + c4];
        __nv_bfloat162 p0 = __floats2bfloat162_rn(v.x, v.y);
        __nv_bfloat162 p1 = __floats2bfloat162_rn(v.z, v.w);
        uint2 u;
        u.x = *(uint32_t*)&p0;
        u.y = *(uint32_t*)&p1;
        *(uint2*)(Bs + r * LDSS + c4 * 4) = u;
    }

    const int aRow = lane & 15,                       aKo = (lane >> 4) << 3;
    const int bRow = (lane & 7) + ((lane >> 4) << 3), bKo = ((lane >> 3) & 1) << 3;
    const int qr = lane >> 2, qc = lane & 3;

    uint32_t aAd[2][2], bAd[4];
    #pragma unroll
    for (int t = 0; t < 2; t++) {
        aAd[0][t] = sptr(smem_raw + SM_A0 + ((wm * 32 + t * 16 + aRow) * LDSS + aKo) * 2);
        aAd[1][t] = aAd[0][t] + (SM_A1 - SM_A0);
    }
    #pragma unroll
    for (int t = 0; t < 4; t++)
        bAd[t] = sptr(Bs + (wn * 64 + t * 16 + bRow) * LDSS + bKo);

    float accA[2][8][4], accB[2][8][4];
    #pragma unroll
    for (int mf = 0; mf < 2; mf++)        // accB feeds chunk 0's (discarded) epilogue
        #pragma unroll
        for (int nf = 0; nf < 8; nf++)
            #pragma unroll
            for (int j = 0; j < 4; j++) accB[mf][nf][j] = 0.f;

    #pragma unroll 1
    for (int mc = 0; mc < NCHUNKS; mc += 2) {
        chunk_step(mc,     accA, accB, aAd[0], bAd, smem_raw + SM_A0, red_s, tid, wm, wn, qr, qc);
        chunk_step(mc + 1, accB, accA, aAd[1], bAd, smem_raw + SM_A1, red_s, tid, wm, wn, qr, qc);
    }

    // tail epilogue for chunk NCHUNKS-1 (in accB)
    __syncthreads();                      // last merge finished reading red_s
    {
        float s4[4] = {0.f, 0.f, 0.f, 0.f};
        #pragma unroll
        for (int mf = 0; mf < 2; mf++)
            #pragma unroll
            for (int hi = 0; hi < 2; hi++)
                #pragma unroll
                for (int nf = 0; nf < 8; nf++)
                    #pragma unroll
                    for (int j = 0; j < 2; j++)
                        s4[mf * 2 + hi] += exp2f(accB[mf][nf][hi * 2 + j] - SHIFT);
        #pragma unroll
        for (int mf = 0; mf < 2; mf++)
            #pragma unroll
            for (int hi = 0; hi < 2; hi++) {
                int rl = wm * 32 + mf * 16 + hi * 8 + qr;
                red_s[rl * REDP + wn * 4 + qc] = s4[mf * 2 + hi];
            }
        __syncthreads();
        if (tid < MCHUNK) {
            float S = red_s[tid * REDP];
            #pragma unroll
            for (int i = 1; i < 16; i++) S += red_s[tid * REDP + i];
            g_ps[(size_t)blockIdx.x * BATCH + (NCHUNKS - 1) * MCHUNK + tid] = S;
        }
    }
}

// ---------------------------------------------------------------- cross-block merge: plain sum (fixed shift)
__global__ void lse_kernel() {
    int row = blockIdx.x;
    int tid = threadIdx.x;  // 256
    float S = 0.f;
    for (int b = tid; b < NBLK; b += 256)
        S += g_ps[(size_t)b * BATCH + row];
    for (int off = 16; off; off >>= 1) S += __shfl_xor_sync(~0u, S, off);
    __shared__ float ss[8];
    if ((tid & 31) == 0) ss[tid >> 5] = S;
    __syncthreads();
    if (tid == 0) {
        float Sv = 0.f;
        #pragma unroll
        for (int i = 0; i < 8; i++) Sv += ss[i];
        g_rownll[row] = (SHIFT + log2f(Sv)) * LN2F - g_tlogit[row];
    }
}

__global__ void mean_kernel(float* __restrict__ out) {
    __shared__ float sm[32];
    int tid = threadIdx.x;  // 1024
    float v = g_rownll[tid];
    for (int off = 16; off; off >>= 1) v += __shfl_xor_sync(~0u, v, off);
    if ((tid & 31) == 0) sm[tid >> 5] = v;
    __syncthreads();
    if (tid < 32) {
        float x = sm[tid];
        for (int off = 16; off; off >>= 1) x += __shfl_xor_sync(~0u, x, off);
        if (tid == 0) out[0] = x / (float)BATCH;
    }
}

// ---------------------------------------------------------------- launch
extern "C" void kernel_launch(void* const* d_in, const int* in_sizes, int n_in,
                              void* d_out, int out_size) {
    const float* a   = (const float*)d_in[0];   // inputs   [1024,256] f32
    const int*   t32 = (const int*)d_in[1];     // targets  [1024] i64/i32
    const float* f   = (const float*)d_in[2];   // features [100000,256] f32
    float* out = (float*)d_out;

    cudaFuncSetAttribute(gemm_lse_kernel,
                         cudaFuncAttributeMaxDynamicSharedMemorySize, SMEM_BYTES);

    prep_kernel<<<(BATCH * NF + 255) / 256, 256>>>(a);
    detect_kernel<<<1, 32>>>(t32);
    tlogit_kernel<<<BATCH, 256>>>(a, t32, f);
    gemm_lse_kernel<<<NBLK, 256, SMEM_BYTES>>>(f);
    lse_kernel<<<BATCH, 256>>>();
    mean_kernel<<<1, 1024>>>(out);
}

// round 12
// speedup vs baseline: 1.0397x; 1.0188x over previous
#include <cuda_runtime.h>
#include <cuda_bf16.h>
#include <math.h>
#include <stdint.h>

#define BATCH     1024
#define NF        256
#define NS        100000
#define INV_TEMP  20.0f
#define LOG2E     1.4426950408889634f
#define LN2F      0.6931471805599453f
#define SCALE2    (INV_TEMP * LOG2E)           /* folded into A at prep */
#define SHIFT     128.0f                       /* fixed softmax shift (log2 domain) */
#define NTILE     352
#define WN        88                            /* cols per warp */
#define NFW       11                            /* 8-col frags per warp */
#define NBLK      ((NS + NTILE - 1) / NTILE)   /* 285 -> 1.93 waves */
#define MCHUNK    64
#define NCHUNKS   (BATCH / MCHUNK)             /* 16 */
#define LDSS      264                          /* 256 + 8 bf16 pad (528B: conflict-free) */
#define REDP      17

#define SM_A      0                                    /* [64][264] bf16 = 33792 */
#define SM_B      (MCHUNK * LDSS * 2)                  /* [352][264] bf16 = 185856 */
#define SM_RED    (SM_B + NTILE * LDSS * 2)            /* [64][17] float */
#define SMEM_BYTES (SM_RED + MCHUNK * REDP * 4 + 64)   /* ~224 KB */

__device__ __nv_bfloat16 g_a_bf16[BATCH * NF];   /* pre-scaled by SCALE2 */
__device__ float g_ps[(size_t)NBLK * BATCH];
__device__ float g_tlogit[BATCH];
__device__ float g_rownll[BATCH];
__device__ int   g_tstride;

// ---------------------------------------------------------------- helpers
__device__ __forceinline__ uint32_t sptr(const void* p) {
    return (uint32_t)__cvta_generic_to_shared(p);
}
__device__ __forceinline__ void ldsm4(uint32_t addr, uint32_t& r0, uint32_t& r1,
                                      uint32_t& r2, uint32_t& r3) {
    asm volatile("ldmatrix.sync.aligned.m8n8.x4.shared.b16 {%0,%1,%2,%3}, [%4];"
                 : "=r"(r0), "=r"(r1), "=r"(r2), "=r"(r3) : "r"(addr));
}
__device__ __forceinline__ void ldsm2(uint32_t addr, uint32_t& r0, uint32_t& r1) {
    asm volatile("ldmatrix.sync.aligned.m8n8.x2.shared.b16 {%0,%1}, [%2];"
                 : "=r"(r0), "=r"(r1) : "r"(addr));
}
__device__ __forceinline__ void mma16816(float c[4], const uint32_t a[4],
                                         uint32_t b0, uint32_t b1) {
    asm volatile(
        "mma.sync.aligned.m16n8k16.row.col.f32.bf16.bf16.f32 "
        "{%0,%1,%2,%3},{%4,%5,%6,%7},{%8,%9},{%0,%1,%2,%3};"
        : "+f"(c[0]), "+f"(c[1]), "+f"(c[2]), "+f"(c[3])
        : "r"(a[0]), "r"(a[1]), "r"(a[2]), "r"(a[3]), "r"(b0), "r"(b1));
}
#define CP_ASYNC16(dst, src) \
    asm volatile("cp.async.cg.shared.global [%0], [%1], 16;" :: "r"(dst), "l"(src) : "memory")
#define CP_COMMIT() asm volatile("cp.async.commit_group;" ::: "memory")
#define CP_WAIT0()  asm volatile("cp.async.wait_group 0;" ::: "memory")

// ---------------------------------------------------------------- prep kernels
__global__ void prep_kernel(const float* __restrict__ a) {
    int i = blockIdx.x * blockDim.x + threadIdx.x;
    if (i < BATCH * NF) g_a_bf16[i] = __float2bfloat16(a[i] * SCALE2);
}

__global__ void detect_kernel(const int* __restrict__ t32) {
    if (threadIdx.x == 0 && blockIdx.x == 0) {
        int s = 2;
        for (int i = 1; i < 512; i += 2)
            if (t32[i] != 0) { s = 1; break; }
        g_tstride = s;
    }
}

__global__ void tlogit_kernel(const float* __restrict__ a,
                              const int* __restrict__ t32,
                              const float* __restrict__ f) {
    int row = blockIdx.x;
    int tid = threadIdx.x;  // 256
    long long tgt = (long long)t32[row * g_tstride];
    float p = a[row * NF + tid] * f[tgt * NF + tid];
    for (int off = 16; off; off >>= 1) p += __shfl_xor_sync(~0u, p, off);
    __shared__ float sm[8];
    if ((tid & 31) == 0) sm[tid >> 5] = p;
    __syncthreads();
    if (tid == 0) {
        float s = 0.f;
        #pragma unroll
        for (int w = 0; w < 8; w++) s += sm[w];
        g_tlogit[row] = s * INV_TEMP;
    }
}

// ---------------------------------------------------------------- fused GEMM + fixed-shift softmax partials
extern __shared__ char smem_raw[];

__global__ void __launch_bounds__(256, 1) gemm_lse_kernel(const float* __restrict__ feats) {
    __nv_bfloat16* Bs = (__nv_bfloat16*)(smem_raw + SM_B);   // [352][264]
    float* red_s = (float*)(smem_raw + SM_RED);              // [64][17]

    const int tid  = threadIdx.x;                    // 256 threads, 8 warps
    const int lane = tid & 31, warp = tid >> 5;
    const int wm = warp & 1, wn = warp >> 1;         // 2x4 grid, 32x88 warp tiles
    const int nbase = blockIdx.x * NTILE;

    // Issue A chunk 0 (single-buffer pipeline)
    {
        const char* src_base = (const char*)g_a_bf16;
        #pragma unroll
        for (int it = 0; it < 8; it++) {
            int i = tid + it * 256;                  // [0, 2048)
            int r = i >> 5, c8 = i & 31;
            CP_ASYNC16(sptr(smem_raw + SM_A + (r * LDSS + c8 * 8) * 2),
                       src_base + (size_t)r * 512 + c8 * 16);
        }
        CP_COMMIT();
    }

    // Load feature slab once (fp32 -> bf16): 352 rows; OOB rows -> 0
    for (int i = tid; i < NTILE * (NF / 4); i += 256) {
        int r  = i >> 6;
        int c4 = i & 63;
        int srow = nbase + r;
        float4 v = make_float4(0.f, 0.f, 0.f, 0.f);
        if (srow < NS) v = ((const float4*)feats)[(size_t)srow * (NF / 4) + c4];
        __nv_bfloat162 p0 = __floats2bfloat162_rn(v.x, v.y);
        __nv_bfloat162 p1 = __floats2bfloat162_rn(v.z, v.w);
        uint2 u;
        u.x = *(uint32_t*)&p0;
        u.y = *(uint32_t*)&p1;
        *(uint2*)(Bs + r * LDSS + c4 * 4) = u;
    }

    const int aRow = lane & 15,                       aKo = (lane >> 4) << 3;
    const int bRow = (lane & 7) + ((lane >> 4) << 3), bKo = ((lane >> 3) & 1) << 3;
    const int bKo2 = ((lane >> 3) & 1) << 3;          // for ldsm2 tail (lanes 0-15)
    const int qr = lane >> 2, qc = lane & 3;

    uint32_t aAd[2], bAd[5], bAdT;
    #pragma unroll
    for (int t = 0; t < 2; t++)
        aAd[t] = sptr(smem_raw + SM_A + ((wm * 32 + t * 16 + aRow) * LDSS + aKo) * 2);
    #pragma unroll
    for (int t = 0; t < 5; t++)
        bAd[t] = sptr(Bs + (wn * WN + t * 16 + bRow) * LDSS + bKo);
    bAdT = sptr(Bs + (wn * WN + 80 + (lane & 7)) * LDSS + bKo2);

    float acc[2][NFW][4];

    #pragma unroll 1
    for (int mc = 0; mc < NCHUNKS; mc++) {
        CP_WAIT0();
        __syncthreads();                  // A[mc] visible; prior merge done

        #pragma unroll
        for (int mf = 0; mf < 2; mf++)
            #pragma unroll
            for (int nf = 0; nf < NFW; nf++)
                #pragma unroll
                for (int j = 0; j < 4; j++) acc[mf][nf][j] = 0.f;

        uint32_t af[2][2][4];
        uint32_t bf[2][NFW][2];
        #pragma unroll
        for (int t = 0; t < 2; t++)
            ldsm4(aAd[t], af[0][t][0], af[0][t][1], af[0][t][2], af[0][t][3]);
        #pragma unroll
        for (int t = 0; t < 5; t++)
            ldsm4(bAd[t], bf[0][2*t][0], bf[0][2*t][1], bf[0][2*t+1][0], bf[0][2*t+1][1]);
        ldsm2(bAdT, bf[0][10][0], bf[0][10][1]);

        #pragma unroll
        for (int ks = 0; ks < 16; ks++) {
            const int cur = ks & 1, nx = cur ^ 1;
            if (ks < 15) {
                const uint32_t off = (uint32_t)(ks + 1) * 32;
                #pragma unroll
                for (int t = 0; t < 2; t++)
                    ldsm4(aAd[t] + off, af[nx][t][0], af[nx][t][1], af[nx][t][2], af[nx][t][3]);
                #pragma unroll
                for (int t = 0; t < 5; t++)
                    ldsm4(bAd[t] + off, bf[nx][2*t][0], bf[nx][2*t][1], bf[nx][2*t+1][0], bf[nx][2*t+1][1]);
                ldsm2(bAdT + off, bf[nx][10][0], bf[nx][10][1]);
            }
            #pragma unroll
            for (int mf = 0; mf < 2; mf++)
                #pragma unroll
                for (int nf = 0; nf < NFW; nf++)
                    mma16816(acc[mf][nf], af[cur][mf], bf[cur][nf][0], bf[cur][nf][1]);
        }

        __syncthreads();                  // A buffer free for refill

        if (mc + 1 < NCHUNKS) {           // refill with A[mc+1]
            const char* src_base = (const char*)g_a_bf16 + (size_t)(mc + 1) * MCHUNK * 512;
            #pragma unroll
            for (int it = 0; it < 8; it++) {
                int i = tid + it * 256;
                int r = i >> 5, c8 = i & 31;
                CP_ASYNC16(sptr(smem_raw + SM_A + (r * LDSS + c8 * 8) * 2),
                           src_base + (size_t)r * 512 + c8 * 16);
            }
            CP_COMMIT();
        }

        // serial fixed-shift epilogue (overlaps the cp.async flight above);
        // OOB cols come from zero B rows -> exp2(-128) ~ 0, no predicates
        #pragma unroll
        for (int mf = 0; mf < 2; mf++) {
            #pragma unroll
            for (int hi = 0; hi < 2; hi++) {
                float s = 0.f;
                #pragma unroll
                for (int nf = 0; nf < NFW; nf++)
                    #pragma unroll
                    for (int j = 0; j < 2; j++)
                        s += exp2f(acc[mf][nf][hi * 2 + j] - SHIFT);
                int rl = wm * 32 + mf * 16 + hi * 8 + qr;
                red_s[rl * REDP + wn * 4 + qc] = s;
            }
        }

        __syncthreads();                  // red partials visible

        if (tid < MCHUNK) {               // 16-way merge; skew absorbed next chunk
            float S = red_s[tid * REDP];
            #pragma unroll
            for (int i = 1; i < 16; i++) S += red_s[tid * REDP + i];
            g_ps[(size_t)blockIdx.x * BATCH + mc * MCHUNK + tid] = S;
        }
    }
}

// ---------------------------------------------------------------- cross-block merge: plain sum (fixed shift)
__global__ void lse_kernel() {
    int row = blockIdx.x;
    int tid = threadIdx.x;  // 256
    float S = 0.f;
    for (int b = tid; b < NBLK; b += 256)
        S += g_ps[(size_t)b * BATCH + row];
    for (int off = 16; off; off >>= 1) S += __shfl_xor_sync(~0u, S, off);
    __shared__ float ss[8];
    if ((tid & 31) == 0) ss[tid >> 5] = S;
    __syncthreads();
    if (tid == 0) {
        float Sv = 0.f;
        #pragma unroll
        for (int i = 0; i < 8; i++) Sv += ss[i];
        g_rownll[row] = (SHIFT + log2f(Sv)) * LN2F - g_tlogit[row];
    }
}

__global__ void mean_kernel(float* __restrict__ out) {
    __shared__ float sm[32];
    int tid = threadIdx.x;  // 1024
    float v = g_rownll[tid];
    for (int off = 16; off; off >>= 1) v += __shfl_xor_sync(~0u, v, off);
    if ((tid & 31) == 0) sm[tid >> 5] = v;
    __syncthreads();
    if (tid < 32) {
        float x = sm[tid];
        for (int off = 16; off; off >>= 1) x += __shfl_xor_sync(~0u, x, off);
        if (tid == 0) out[0] = x / (float)BATCH;
    }
}

// ---------------------------------------------------------------- launch
extern "C" void kernel_launch(void* const* d_in, const int* in_sizes, int n_in,
                              void* d_out, int out_size) {
    const float* a   = (const float*)d_in[0];   // inputs   [1024,256] f32
    const int*   t32 = (const int*)d_in[1];     // targets  [1024] i64/i32
    const float* f   = (const float*)d_in[2];   // features [100000,256] f32
    float* out = (float*)d_out;

    cudaFuncSetAttribute(gemm_lse_kernel,
                         cudaFuncAttributeMaxDynamicSharedMemorySize, SMEM_BYTES);

    prep_kernel<<<(BATCH * NF + 255) / 256, 256>>>(a);
    detect_kernel<<<1, 32>>>(t32);
    tlogit_kernel<<<BATCH, 256>>>(a, t32, f);
    gemm_lse_kernel<<<NBLK, 256, SMEM_BYTES>>>(f);
    lse_kernel<<<BATCH, 256>>>();
    mean_kernel<<<1, 1024>>>(out);
}

// round 13
// speedup vs baseline: 1.1050x; 1.0628x over previous
#include <cuda_runtime.h>
#include <cuda_bf16.h>
#include <math.h>
#include <stdint.h>

#define BATCH     1024
#define NF        256
#define NS        100000
#define INV_TEMP  20.0f
#define LOG2E     1.4426950408889634f
#define LN2F      0.6931471805599453f
#define SCALE2    (INV_TEMP * LOG2E)           /* folded into A at prep */
#define SHIFT     128.0f                       /* fixed softmax shift (log2 domain) */
#define NTILE     352
#define WN        88
#define NFW       11
#define NBLK      ((NS + NTILE - 1) / NTILE)   /* 285 -> 1.93 waves */
#define MCHUNK    64
#define NCHUNKS   (BATCH / MCHUNK)             /* 16 */
#define LDSS      264                          /* 256 + 8 bf16 pad */
#define REDP      17

#define SM_A      0                                    /* [64][264] bf16 = 33792 */
#define SM_B      (MCHUNK * LDSS * 2)                  /* [352][264] bf16 = 185856 */
#define SM_RED    (SM_B + NTILE * LDSS * 2)
#define SMEM_BYTES (SM_RED + MCHUNK * REDP * 4 + 64)   /* ~224 KB */

__device__ __nv_bfloat16 g_a_bf16[BATCH * NF];   /* pre-scaled by SCALE2 */
__device__ float g_ps[(size_t)NBLK * BATCH];
__device__ float g_tlogit[BATCH];
__device__ float g_rownll[BATCH];
__device__ int   g_tstride;

// ---------------------------------------------------------------- helpers
__device__ __forceinline__ uint32_t sptr(const void* p) {
    return (uint32_t)__cvta_generic_to_shared(p);
}
__device__ __forceinline__ void ldsm4(uint32_t addr, uint32_t& r0, uint32_t& r1,
                                      uint32_t& r2, uint32_t& r3) {
    asm volatile("ldmatrix.sync.aligned.m8n8.x4.shared.b16 {%0,%1,%2,%3}, [%4];"
                 : "=r"(r0), "=r"(r1), "=r"(r2), "=r"(r3) : "r"(addr));
}
__device__ __forceinline__ void ldsm2(uint32_t addr, uint32_t& r0, uint32_t& r1) {
    asm volatile("ldmatrix.sync.aligned.m8n8.x2.shared.b16 {%0,%1}, [%2];"
                 : "=r"(r0), "=r"(r1) : "r"(addr));
}
__device__ __forceinline__ void mma16816(float c[4], const uint32_t a[4],
                                         uint32_t b0, uint32_t b1) {
    asm volatile(
        "mma.sync.aligned.m16n8k16.row.col.f32.bf16.bf16.f32 "
        "{%0,%1,%2,%3},{%4,%5,%6,%7},{%8,%9},{%0,%1,%2,%3};"
        : "+f"(c[0]), "+f"(c[1]), "+f"(c[2]), "+f"(c[3])
        : "r"(a[0]), "r"(a[1]), "r"(a[2]), "r"(a[3]), "r"(b0), "r"(b1));
}
#define CP_ASYNC16(dst, src) \
    asm volatile("cp.async.cg.shared.global [%0], [%1], 16;" :: "r"(dst), "l"(src) : "memory")
#define CP_COMMIT() asm volatile("cp.async.commit_group;" ::: "memory")
#define CP_WAIT0()  asm volatile("cp.async.wait_group 0;" ::: "memory")

// ---------------------------------------------------------------- prep kernels
__global__ void prep_kernel(const float* __restrict__ a) {
    int i = blockIdx.x * blockDim.x + threadIdx.x;
    if (i < BATCH * NF) g_a_bf16[i] = __float2bfloat16(a[i] * SCALE2);
}

__global__ void detect_kernel(const int* __restrict__ t32) {
    if (threadIdx.x == 0 && blockIdx.x == 0) {
        int s = 2;
        for (int i = 1; i < 512; i += 2)
            if (t32[i] != 0) { s = 1; break; }
        g_tstride = s;
    }
}

__global__ void tlogit_kernel(const float* __restrict__ a,
                              const int* __restrict__ t32,
                              const float* __restrict__ f) {
    int row = blockIdx.x;
    int tid = threadIdx.x;  // 256
    long long tgt = (long long)t32[row * g_tstride];
    float p = a[row * NF + tid] * f[tgt * NF + tid];
    for (int off = 16; off; off >>= 1) p += __shfl_xor_sync(~0u, p, off);
    __shared__ float sm[8];
    if ((tid & 31) == 0) sm[tid >> 5] = p;
    __syncthreads();
    if (tid == 0) {
        float s = 0.f;
        #pragma unroll
        for (int w = 0; w < 8; w++) s += sm[w];
        g_tlogit[row] = s * INV_TEMP;
    }
}

// ---------------------------------------------------------------- chunk body
extern __shared__ char smem_raw[];

__device__ __forceinline__ void chunk_step(
    int mc,
    float (&accC)[2][NFW][4], float (&accP)[2][NFW][4],
    const uint32_t (&aAd)[2], const uint32_t (&bAd)[5], uint32_t bAdT,
    float* red_s, int tid, int wm, int wn, int qr, int qc)
{
    CP_WAIT0();
    __syncthreads();                      // A[mc] ready; prior red_s merge done

    #pragma unroll
    for (int mf = 0; mf < 2; mf++)
        #pragma unroll
        for (int nf = 0; nf < NFW; nf++)
            #pragma unroll
            for (int j = 0; j < 4; j++) accC[mf][nf][j] = 0.f;

    float sprev[4] = {0.f, 0.f, 0.f, 0.f};

    // single-buffered fragments: LDSM at top of each kstep, MMAs after;
    // interleaved exp2 of accP fills the latency gap.
    uint32_t af[2][4];
    uint32_t bf[NFW][2];

    #pragma unroll
    for (int ks = 0; ks < 16; ks++) {
        const uint32_t off = (uint32_t)ks * 32;
        #pragma unroll
        for (int t = 0; t < 2; t++)
            ldsm4(aAd[t] + off, af[t][0], af[t][1], af[t][2], af[t][3]);
        #pragma unroll
        for (int t = 0; t < 5; t++)
            ldsm4(bAd[t] + off, bf[2*t][0], bf[2*t][1], bf[2*t+1][0], bf[2*t+1][1]);
        ldsm2(bAdT + off, bf[10][0], bf[10][1]);

        // interleaved epilogue: 6 elements/kstep of the previous chunk (88 total)
        #pragma unroll
        for (int t = 0; t < 6; t++) {
            const int e = ks * 6 + t;
            if (e < 88) {
                const int mf = e / 44, r = e - mf * 44;
                const int nf = r >> 2, hi = (r >> 1) & 1, j = r & 1;
                sprev[mf * 2 + hi] += exp2f(accP[mf][nf][hi * 2 + j] - SHIFT);
            }
        }

        #pragma unroll
        for (int mf = 0; mf < 2; mf++)
            #pragma unroll
            for (int nf = 0; nf < NFW; nf++)
                mma16816(accC[mf][nf], af[mf], bf[nf][0], bf[nf][1]);
    }

    if (mc > 0) {                         // store prev chunk's per-quad sums
        #pragma unroll
        for (int t = 0; t < 4; t++) {
            const int mf = t >> 1, hi = t & 1;
            int rl = wm * 32 + mf * 16 + hi * 8 + qr;
            red_s[rl * REDP + wn * 4 + qc] = sprev[t];
        }
    }

    __syncthreads();                      // A buffer free + red partials visible

    if (mc + 1 < NCHUNKS) {               // refill A with chunk mc+1
        const char* src_base = (const char*)g_a_bf16 + (size_t)(mc + 1) * MCHUNK * 512;
        #pragma unroll
        for (int it = 0; it < 8; it++) {
            int i = tid + it * 256;
            int r = i >> 5, c8 = i & 31;
            CP_ASYNC16(sptr(smem_raw + SM_A + (r * LDSS + c8 * 8) * 2),
                       src_base + (size_t)r * 512 + c8 * 16);
        }
        CP_COMMIT();
    }

    if (mc > 0 && tid < MCHUNK) {         // merge prev chunk; skew absorbed later
        float S = red_s[tid * REDP];
        #pragma unroll
        for (int i = 1; i < 16; i++) S += red_s[tid * REDP + i];
        g_ps[(size_t)blockIdx.x * BATCH + (mc - 1) * MCHUNK + tid] = S;
    }
}

// ---------------------------------------------------------------- fused GEMM + fixed-shift softmax partials
__global__ void __launch_bounds__(256, 1) gemm_lse_kernel(const float* __restrict__ feats) {
    __nv_bfloat16* Bs = (__nv_bfloat16*)(smem_raw + SM_B);   // [352][264]
    float* red_s = (float*)(smem_raw + SM_RED);              // [64][17]

    const int tid  = threadIdx.x;                    // 256 threads, 8 warps
    const int lane = tid & 31, warp = tid >> 5;
    const int wm = warp & 1, wn = warp >> 1;         // 2x4 grid, 32x88 warp tiles
    const int nbase = blockIdx.x * NTILE;

    // Issue A chunk 0
    {
        const char* src_base = (const char*)g_a_bf16;
        #pragma unroll
        for (int it = 0; it < 8; it++) {
            int i = tid + it * 256;
            int r = i >> 5, c8 = i & 31;
            CP_ASYNC16(sptr(smem_raw + SM_A + (r * LDSS + c8 * 8) * 2),
                       src_base + (size_t)r * 512 + c8 * 16);
        }
        CP_COMMIT();
    }

    // Load feature slab once (fp32 -> bf16): 352 rows; OOB rows -> 0
    for (int i = tid; i < NTILE * (NF / 4); i += 256) {
        int r  = i >> 6;
        int c4 = i & 63;
        int srow = nbase + r;
        float4 v = make_float4(0.f, 0.f, 0.f, 0.f);
        if (srow < NS) v = ((const float4*)feats)[(size_t)srow * (NF / 4) + c4];
        __nv_bfloat162 p0 = __floats2bfloat162_rn(v.x, v.y);
        __nv_bfloat162 p1 = __floats2bfloat162_rn(v.z, v.w);
        uint2 u;
        u.x = *(uint32_t*)&p0;
        u.y = *(uint32_t*)&p1;
        *(uint2*)(Bs + r * LDSS + c4 * 4) = u;
    }

    const int aRow = lane & 15,                       aKo = (lane >> 4) << 3;
    const int bRow = (lane & 7) + ((lane >> 4) << 3), bKo = ((lane >> 3) & 1) << 3;
    const int bKo2 = ((lane >> 3) & 1) << 3;
    const int qr = lane >> 2, qc = lane & 3;

    uint32_t aAd[2], bAd[5], bAdT;
    #pragma unroll
    for (int t = 0; t < 2; t++)
        aAd[t] = sptr(smem_raw + SM_A + ((wm * 32 + t * 16 + aRow) * LDSS + aKo) * 2);
    #pragma unroll
    for (int t = 0; t < 5; t++)
        bAd[t] = sptr(Bs + (wn * WN + t * 16 + bRow) * LDSS + bKo);
    bAdT = sptr(Bs + (wn * WN + 80 + (lane & 7)) * LDSS + bKo2);

    float accA[2][NFW][4], accB[2][NFW][4];
    #pragma unroll
    for (int mf = 0; mf < 2; mf++)        // accB feeds chunk 0's (discarded) epilogue
        #pragma unroll
        for (int nf = 0; nf < NFW; nf++)
            #pragma unroll
            for (int j = 0; j < 4; j++) accB[mf][nf][j] = 0.f;

    #pragma unroll 1
    for (int mc = 0; mc < NCHUNKS; mc += 2) {
        chunk_step(mc,     accA, accB, aAd, bAd, bAdT, red_s, tid, wm, wn, qr, qc);
        chunk_step(mc + 1, accB, accA, aAd, bAd, bAdT, red_s, tid, wm, wn, qr, qc);
    }

    // tail epilogue for chunk NCHUNKS-1 (in accB)
    __syncthreads();                      // last merge finished reading red_s
    {
        float s4[4] = {0.f, 0.f, 0.f, 0.f};
        #pragma unroll
        for (int mf = 0; mf < 2; mf++)
            #pragma unroll
            for (int hi = 0; hi < 2; hi++)
                #pragma unroll
                for (int nf = 0; nf < NFW; nf++)
                    #pragma unroll
                    for (int j = 0; j < 2; j++)
                        s4[mf * 2 + hi] += exp2f(accB[mf][nf][hi * 2 + j] - SHIFT);
        #pragma unroll
        for (int t = 0; t < 4; t++) {
            const int mf = t >> 1, hi = t & 1;
            int rl = wm * 32 + mf * 16 + hi * 8 + qr;
            red_s[rl * REDP + wn * 4 + qc] = s4[t];
        }
        __syncthreads();
        if (tid < MCHUNK) {
            float S = red_s[tid * REDP];
            #pragma unroll
            for (int i = 1; i < 16; i++) S += red_s[tid * REDP + i];
            g_ps[(size_t)blockIdx.x * BATCH + (NCHUNKS - 1) * MCHUNK + tid] = S;
        }
    }
}

// ---------------------------------------------------------------- cross-block merge: plain sum (fixed shift)
__global__ void lse_kernel() {
    int row = blockIdx.x;
    int tid = threadIdx.x;  // 256
    float S = 0.f;
    for (int b = tid; b < NBLK; b += 256)
        S += g_ps[(size_t)b * BATCH + row];
    for (int off = 16; off; off >>= 1) S += __shfl_xor_sync(~0u, S, off);
    __shared__ float ss[8];
    if ((tid & 31) == 0) ss[tid >> 5] = S;
    __syncthreads();
    if (tid == 0) {
        float Sv = 0.f;
        #pragma unroll
        for (int i = 0; i < 8; i++) Sv += ss[i];
        g_rownll[row] = (SHIFT + log2f(Sv)) * LN2F - g_tlogit[row];
    }
}

__global__ void mean_kernel(float* __restrict__ out) {
    __shared__ float sm[32];
    int tid = threadIdx.x;  // 1024
    float v = g_rownll[tid];
    for (int off = 16; off; off >>= 1) v += __shfl_xor_sync(~0u, v, off);
    if ((tid & 31) == 0) sm[tid >> 5] = v;
    __syncthreads();
    if (tid < 32) {
        float x = sm[tid];
        for (int off = 16; off; off >>= 1) x += __shfl_xor_sync(~0u, x, off);
        if (tid == 0) out[0] = x / (float)BATCH;
    }
}

// ---------------------------------------------------------------- launch
extern "C" void kernel_launch(void* const* d_in, const int* in_sizes, int n_in,
                              void* d_out, int out_size) {
    const float* a   = (const float*)d_in[0];   // inputs   [1024,256] f32
    const int*   t32 = (const int*)d_in[1];     // targets  [1024] i64/i32
    const float* f   = (const float*)d_in[2];   // features [100000,256] f32
    float* out = (float*)d_out;

    cudaFuncSetAttribute(gemm_lse_kernel,
                         cudaFuncAttributeMaxDynamicSharedMemorySize, SMEM_BYTES);

    prep_kernel<<<(BATCH * NF + 255) / 256, 256>>>(a);
    detect_kernel<<<1, 32>>>(t32);
    tlogit_kernel<<<BATCH, 256>>>(a, t32, f);
    gemm_lse_kernel<<<NBLK, 256, SMEM_BYTES>>>(f);
    lse_kernel<<<BATCH, 256>>>();
    mean_kernel<<<1, 1024>>>(out);
}

// round 14
// speedup vs baseline: 1.1244x; 1.0175x over previous
#include <cuda_runtime.h>
#include <cuda_bf16.h>
#include <math.h>
#include <stdint.h>

#define BATCH     1024
#define NF        256
#define NS        100000
#define INV_TEMP  20.0f
#define LOG2E     1.4426950408889634f
#define LN2F      0.6931471805599453f
#define SCALE2    (INV_TEMP * LOG2E)           /* folded into A at pack time */
#define SHIFT     128.0f                       /* fixed softmax shift (log2 domain) */
#define NTILE     352
#define WN        88
#define NFW       11
#define NBLK      ((NS + NTILE - 1) / NTILE)   /* 285 -> 1.93 waves */
#define MCHUNK    64
#define NCHUNKS   (BATCH / MCHUNK)             /* 16 */
#define LDSS      264                          /* 256 + 8 bf16 pad */

#define SMEM_BYTES (NTILE * LDSS * 2 + 64)     /* B slab only, ~186 KB */

/* A packed fragment-major: [64 frag16 groups][16 ksteps][32 lanes] x 16B */
__device__ uint4 g_a_pk[64 * 16 * 32];
__device__ float g_pq[(size_t)NBLK * BATCH * 16];  /* per-quad partial sums */
__device__ float g_tlogit[BATCH];
__device__ float g_rownll[BATCH];
__device__ int   g_tstride;

// ---------------------------------------------------------------- helpers
__device__ __forceinline__ uint32_t sptr(const void* p) {
    return (uint32_t)__cvta_generic_to_shared(p);
}
__device__ __forceinline__ void ldsm4(uint32_t addr, uint32_t& r0, uint32_t& r1,
                                      uint32_t& r2, uint32_t& r3) {
    asm volatile("ldmatrix.sync.aligned.m8n8.x4.shared.b16 {%0,%1,%2,%3}, [%4];"
                 : "=r"(r0), "=r"(r1), "=r"(r2), "=r"(r3) : "r"(addr));
}
__device__ __forceinline__ void ldsm2(uint32_t addr, uint32_t& r0, uint32_t& r1) {
    asm volatile("ldmatrix.sync.aligned.m8n8.x2.shared.b16 {%0,%1}, [%2];"
                 : "=r"(r0), "=r"(r1) : "r"(addr));
}
__device__ __forceinline__ void mma16816(float c[4], const uint32_t a[4],
                                         uint32_t b0, uint32_t b1) {
    asm volatile(
        "mma.sync.aligned.m16n8k16.row.col.f32.bf16.bf16.f32 "
        "{%0,%1,%2,%3},{%4,%5,%6,%7},{%8,%9},{%0,%1,%2,%3};"
        : "+f"(c[0]), "+f"(c[1]), "+f"(c[2]), "+f"(c[3])
        : "r"(a[0]), "r"(a[1]), "r"(a[2]), "r"(a[3]), "r"(b0), "r"(b1));
}

// ---------------------------------------------------------------- prep: pack A into frag-major layout
// a-frag word order for m16n8k16 (row-major A): a0=(qr, qc*2), a1=(qr+8, qc*2),
// a2=(qr, qc*2+8), a3=(qr+8, qc*2+8); each word = 2 consecutive-col bf16.
__global__ void prep_kernel(const float* __restrict__ a) {
    int w = blockIdx.x * blockDim.x + threadIdx.x;   // word idx [0, 131072)
    if (w >= 64 * 16 * 32 * 4) return;
    int word = w & 3;
    int lane = (w >> 2) & 31;
    int ks   = (w >> 7) & 15;
    int g    = w >> 11;
    int qr = lane >> 2, qc = lane & 3;
    int row = g * 16 + qr + (word & 1) * 8;
    int col = ks * 16 + qc * 2 + (word >> 1) * 8;
    float f0 = a[row * NF + col]     * SCALE2;
    float f1 = a[row * NF + col + 1] * SCALE2;
    __nv_bfloat162 p = __floats2bfloat162_rn(f0, f1);
    ((uint32_t*)g_a_pk)[w] = *(uint32_t*)&p;
}

__global__ void detect_kernel(const int* __restrict__ t32) {
    if (threadIdx.x == 0 && blockIdx.x == 0) {
        int s = 2;
        for (int i = 1; i < 512; i += 2)
            if (t32[i] != 0) { s = 1; break; }
        g_tstride = s;
    }
}

__global__ void tlogit_kernel(const float* __restrict__ a,
                              const int* __restrict__ t32,
                              const float* __restrict__ f) {
    int row = blockIdx.x;
    int tid = threadIdx.x;  // 256
    long long tgt = (long long)t32[row * g_tstride];
    float p = a[row * NF + tid] * f[tgt * NF + tid];
    for (int off = 16; off; off >>= 1) p += __shfl_xor_sync(~0u, p, off);
    __shared__ float sm[8];
    if ((tid & 31) == 0) sm[tid >> 5] = p;
    __syncthreads();
    if (tid == 0) {
        float s = 0.f;
        #pragma unroll
        for (int w = 0; w < 8; w++) s += sm[w];
        g_tlogit[row] = s * INV_TEMP;
    }
}

// ---------------------------------------------------------------- fused GEMM + fixed-shift softmax partials
extern __shared__ char smem_raw[];

__global__ void __launch_bounds__(256, 1) gemm_lse_kernel(const float* __restrict__ feats) {
    __nv_bfloat16* Bs = (__nv_bfloat16*)smem_raw;    // [352][264]

    const int tid  = threadIdx.x;                    // 256 threads, 8 warps
    const int lane = tid & 31, warp = tid >> 5;
    const int wm = warp & 1, wn = warp >> 1;         // 2x4 grid, 32x88 warp tiles
    const int nbase = blockIdx.x * NTILE;

    // Load feature slab once (fp32 -> bf16): 352 rows; OOB rows -> 0
    for (int i = tid; i < NTILE * (NF / 4); i += 256) {
        int r  = i >> 6;
        int c4 = i & 63;
        int srow = nbase + r;
        float4 v = make_float4(0.f, 0.f, 0.f, 0.f);
        if (srow < NS) v = ((const float4*)feats)[(size_t)srow * (NF / 4) + c4];
        __nv_bfloat162 p0 = __floats2bfloat162_rn(v.x, v.y);
        __nv_bfloat162 p1 = __floats2bfloat162_rn(v.z, v.w);
        uint2 u;
        u.x = *(uint32_t*)&p0;
        u.y = *(uint32_t*)&p1;
        *(uint2*)(Bs + r * LDSS + c4 * 4) = u;
    }

    const int bRow = (lane & 7) + ((lane >> 4) << 3), bKo = ((lane >> 3) & 1) << 3;
    const int bKo2 = ((lane >> 3) & 1) << 3;
    const int qr = lane >> 2, qc = lane & 3;

    uint32_t bAd[5], bAdT;
    #pragma unroll
    for (int t = 0; t < 5; t++)
        bAd[t] = sptr(Bs + (wn * WN + t * 16 + bRow) * LDSS + bKo);
    bAdT = sptr(Bs + (wn * WN + 80 + (lane & 7)) * LDSS + bKo2);

    __syncthreads();                      // the ONLY barrier: B slab ready

    // Rotated chunk order: per-SMSP warp pair offset by 8 chunks so one warp's
    // epilogue always overlaps the other's MMA stream.
    const int mc0 = (2 * warp) & (NCHUNKS - 1);

    float acc[2][NFW][4];
    uint32_t af[2][2][4];                 // double-buffered A frags (via LDG.128)
    uint32_t bf[2][NFW][2];               // double-buffered B frags (via ldsm)

    // preload kstep 0 of first chunk into buffer 0
    #pragma unroll
    for (int mf = 0; mf < 2; mf++) {
        uint4 v = __ldg(&g_a_pk[((mc0 * 4 + wm * 2 + mf) * 16 + 0) * 32 + lane]);
        af[0][mf][0] = v.x; af[0][mf][1] = v.y; af[0][mf][2] = v.z; af[0][mf][3] = v.w;
    }
    #pragma unroll
    for (int t = 0; t < 5; t++)
        ldsm4(bAd[t], bf[0][2*t][0], bf[0][2*t][1], bf[0][2*t+1][0], bf[0][2*t+1][1]);
    ldsm2(bAdT, bf[0][10][0], bf[0][10][1]);

    #pragma unroll 1
    for (int mcc = 0; mcc < NCHUNKS; mcc++) {
        const int mc = (mc0 + mcc) & (NCHUNKS - 1);

        #pragma unroll
        for (int mf = 0; mf < 2; mf++)
            #pragma unroll
            for (int nf = 0; nf < NFW; nf++)
                #pragma unroll
                for (int j = 0; j < 4; j++) acc[mf][nf][j] = 0.f;

        #pragma unroll
        for (int ks = 0; ks < 16; ks++) {
            const int cur = ks & 1, nx = cur ^ 1;
            // prefetch next kstep (wraps into next chunk's kstep 0)
            if (ks < 15 || mcc + 1 < NCHUNKS) {
                const int pmc = (ks < 15) ? mc : ((mc + 1) & (NCHUNKS - 1));
                const int pks = (ks < 15) ? (ks + 1) : 0;
                #pragma unroll
                for (int mf = 0; mf < 2; mf++) {
                    uint4 v = __ldg(&g_a_pk[((pmc * 4 + wm * 2 + mf) * 16 + pks) * 32 + lane]);
                    af[nx][mf][0] = v.x; af[nx][mf][1] = v.y;
                    af[nx][mf][2] = v.z; af[nx][mf][3] = v.w;
                }
                const uint32_t off = (uint32_t)pks * 32;
                #pragma unroll
                for (int t = 0; t < 5; t++)
                    ldsm4(bAd[t] + off, bf[nx][2*t][0], bf[nx][2*t][1],
                          bf[nx][2*t+1][0], bf[nx][2*t+1][1]);
                ldsm2(bAdT + off, bf[nx][10][0], bf[nx][10][1]);
            }
            #pragma unroll
            for (int mf = 0; mf < 2; mf++)
                #pragma unroll
                for (int nf = 0; nf < NFW; nf++)
                    mma16816(acc[mf][nf], af[cur][mf], bf[cur][nf][0], bf[cur][nf][1]);
        }

        // per-warp epilogue: fixed-shift sums, then fire-and-forget STG.
        // Other warps' MMAs keep the tensor pipe busy meanwhile (rotation).
        {
            float s4[4] = {0.f, 0.f, 0.f, 0.f};
            #pragma unroll
            for (int mf = 0; mf < 2; mf++)
                #pragma unroll
                for (int hi = 0; hi < 2; hi++)
                    #pragma unroll
                    for (int nf = 0; nf < NFW; nf++)
                        #pragma unroll
                        for (int j = 0; j < 2; j++)
                            s4[mf * 2 + hi] += exp2f(acc[mf][nf][hi * 2 + j] - SHIFT);
            #pragma unroll
            for (int t = 0; t < 4; t++) {
                const int mf = t >> 1, hi = t & 1;
                int rl = wm * 32 + mf * 16 + hi * 8 + qr;
                g_pq[((size_t)blockIdx.x * BATCH + mc * MCHUNK + rl) * 16 + wn * 4 + qc] = s4[t];
            }
        }
    }
}

// ---------------------------------------------------------------- cross-block merge: plain sum over 285x16 quads
__global__ void lse_kernel() {
    int row = blockIdx.x;
    int tid = threadIdx.x;  // 256
    float S = 0.f;
    const int total = NBLK * 16;
    for (int v = tid; v < total; v += 256) {
        int blk = v >> 4, idx = v & 15;
        S += g_pq[((size_t)blk * BATCH + row) * 16 + idx];
    }
    for (int off = 16; off; off >>= 1) S += __shfl_xor_sync(~0u, S, off);
    __shared__ float ss[8];
    if ((tid & 31) == 0) ss[tid >> 5] = S;
    __syncthreads();
    if (tid == 0) {
        float Sv = 0.f;
        #pragma unroll
        for (int i = 0; i < 8; i++) Sv += ss[i];
        g_rownll[row] = (SHIFT + log2f(Sv)) * LN2F - g_tlogit[row];
    }
}

__global__ void mean_kernel(float* __restrict__ out) {
    __shared__ float sm[32];
    int tid = threadIdx.x;  // 1024
    float v = g_rownll[tid];
    for (int off = 16; off; off >>= 1) v += __shfl_xor_sync(~0u, v, off);
    if ((tid & 31) == 0) sm[tid >> 5] = v;
    __syncthreads();
    if (tid < 32) {
        float x = sm[tid];
        for (int off = 16; off; off >>= 1) x += __shfl_xor_sync(~0u, x, off);
        if (tid == 0) out[0] = x / (float)BATCH;
    }
}

// ---------------------------------------------------------------- launch
extern "C" void kernel_launch(void* const* d_in, const int* in_sizes, int n_in,
                              void* d_out, int out_size) {
    const float* a   = (const float*)d_in[0];   // inputs   [1024,256] f32
    const int*   t32 = (const int*)d_in[1];     // targets  [1024] i64/i32
    const float* f   = (const float*)d_in[2];   // features [100000,256] f32
    float* out = (float*)d_out;

    cudaFuncSetAttribute(gemm_lse_kernel,
                         cudaFuncAttributeMaxDynamicSharedMemorySize, SMEM_BYTES);

    prep_kernel<<<512, 256>>>(a);
    detect_kernel<<<1, 32>>>(t32);
    tlogit_kernel<<<BATCH, 256>>>(a, t32, f);
    gemm_lse_kernel<<<NBLK, 256, SMEM_BYTES>>>(f);
    lse_kernel<<<BATCH, 256>>>();
    mean_kernel<<<1, 1024>>>(out);
}